// round 12
// baseline (speedup 1.0000x reference)
#include <cuda_runtime.h>
#include <cstdint>

// Problem constants: S=16, P=8, N=64, D=128
#define NBLK   128
#define NROW   64
#define DIMD   128
#define STRIDE 132          // fp32 row stride
#define QSTR   68           // int16x2 row stride in u32 (68 mod 32 == 4: LDS.128 conflict-free)
#define NTHR   1024
#define QSCALE 1024.0f
#define RQS    (1.0f / 1024.0f)

// smem floats: sx[64][132], sy[64][132], nx2/rnx/ny2/rny[64], qx[64][68](u32), qy[64][68](u32)
#define SMEM_FLOATS (2 * NROW * STRIDE + 4 * NROW + 2 * NROW * QSTR)

// acc += |a.h0-b.h0| + |a.h1-b.h1|  (signed 16-bit halves, u32 accumulator)
#define VAD(acc, a, b) \
    asm("vabsdiff2.u32.s32.s32.add %0, %1, %2, %0;" : "+r"(acc) : "r"(a), "r"(b))

__device__ __forceinline__ uint32_t pack16(int lo, int hi) {
    return (uint32_t)(lo & 0xFFFF) | ((uint32_t)hi << 16);
}

__global__ void __launch_bounds__(NTHR, 1)
vcmp_kernel(const float* __restrict__ X, const float* __restrict__ Y,
            float* __restrict__ out) {
    extern __shared__ float smem[];
    float* sx  = smem;
    float* sy  = smem + NROW * STRIDE;
    float* nx2 = sy + NROW * STRIDE;
    float* rnx = nx2 + NROW;
    float* ny2 = rnx + NROW;
    float* rny = ny2 + NROW;
    uint32_t* qx = (uint32_t*)(rny + NROW);
    uint32_t* qy = qx + NROW * QSTR;

    const int blk = blockIdx.x;
    const int t   = threadIdx.x;
    const int wid = t >> 5;
    const int lid = t & 31;

    // ---- Load x, y -> fp32 smem + quantized int16 smem ----
    const float4* xg = (const float4*)(X + (size_t)blk * NROW * DIMD);
    const float4* yg = (const float4*)(Y + (size_t)blk * NROW * DIMD);
#pragma unroll
    for (int k = 0; k < 2; k++) {
        int g    = k * NTHR + t;    // float4 index, 0..2047
        int row  = g >> 5;
        int col4 = (g & 31) * 4;
        float4 xv = xg[g];
        float4 yv = yg[g];
        *(float4*)(sx + row * STRIDE + col4) = xv;
        *(float4*)(sy + row * STRIDE + col4) = yv;

        uint2 qxv, qyv;
        qxv.x = pack16(__float2int_rn(xv.x * QSCALE), __float2int_rn(xv.y * QSCALE));
        qxv.y = pack16(__float2int_rn(xv.z * QSCALE), __float2int_rn(xv.w * QSCALE));
        qyv.x = pack16(__float2int_rn(yv.x * QSCALE), __float2int_rn(yv.y * QSCALE));
        qyv.y = pack16(__float2int_rn(yv.z * QSCALE), __float2int_rn(yv.w * QSCALE));
        *(uint2*)(qx + row * QSTR + (g & 31) * 2) = qxv;
        *(uint2*)(qy + row * QSTR + (g & 31) * 2) = qyv;
    }
    __syncthreads();

    // ---- Per-row norms (threads 0..127) ----
    if (t < 128) {
        const float* r = (t < NROW) ? (sx + t * STRIDE) : (sy + (t - NROW) * STRIDE);
        float ss = 0.f;
#pragma unroll 8
        for (int d = 0; d < DIMD; d++) ss = fmaf(r[d], r[d], ss);
        float rn = 1.0f / fmaxf(sqrtf(ss), 1e-12f);
        if (t < NROW) { nx2[t] = ss; rnx[t] = rn; }
        else          { ny2[t - NROW] = ss; rny[t - NROW] = rn; }
    }
    __syncthreads();

    // ---- Gram via mma.sync m16n8k8 tf32 (R6-proven): C = dot(x_n, y_m) ----
    const int g_ = lid >> 2;
    const int tg = lid & 3;
    const int n0 = (wid >> 3) * 16;
    const int m0 = (wid & 7) * 8;

    float c0 = 0.f, c1 = 0.f, c2 = 0.f, c3 = 0.f;
    {
        const uint32_t* pa = (const uint32_t*)(sx + (n0 + g_) * STRIDE + tg);
        const uint32_t* pb = (const uint32_t*)(sy + (m0 + g_) * STRIDE + tg);
#pragma unroll
        for (int kk = 0; kk < 16; kk++) {
            const int d0 = kk * 8;
            uint32_t a0 = pa[d0];
            uint32_t a1 = pa[8 * STRIDE + d0];
            uint32_t a2 = pa[d0 + 4];
            uint32_t a3 = pa[8 * STRIDE + d0 + 4];
            uint32_t b0 = pb[d0];
            uint32_t b1 = pb[d0 + 4];
            asm volatile(
                "mma.sync.aligned.m16n8k8.row.col.f32.tf32.tf32.f32 "
                "{%0,%1,%2,%3}, {%4,%5,%6,%7}, {%8,%9}, {%0,%1,%2,%3};"
                : "+f"(c0), "+f"(c1), "+f"(c2), "+f"(c3)
                : "r"(a0), "r"(a1), "r"(a2), "r"(a3), "r"(b0), "r"(b1));
        }
    }

    // ---- L1 loop: int16 SAD, one vabsdiff2.add per 2 elements per pair ----
    // n = 2*wid + i, m = lid + 32*j; x loads broadcast, y loads conflict-free
    const uint32_t* xq = qx + (wid * 2) * QSTR;
    const uint32_t* yq = qy + lid * QSTR;

    uint32_t acc[2][2][2] = {{{0u,0u},{0u,0u}},{{0u,0u},{0u,0u}}};

#pragma unroll
    for (int d4 = 0; d4 < 64; d4 += 4) {    // 16 iters, 8 elements each
        uint4 x0 = *(const uint4*)(xq + d4);
        uint4 x1 = *(const uint4*)(xq + QSTR + d4);
        uint4 y0 = *(const uint4*)(yq + d4);
        uint4 y1 = *(const uint4*)(yq + 32 * QSTR + d4);

        VAD(acc[0][0][0], x0.x, y0.x); VAD(acc[0][0][1], x0.y, y0.y);
        VAD(acc[0][0][0], x0.z, y0.z); VAD(acc[0][0][1], x0.w, y0.w);

        VAD(acc[0][1][0], x0.x, y1.x); VAD(acc[0][1][1], x0.y, y1.y);
        VAD(acc[0][1][0], x0.z, y1.z); VAD(acc[0][1][1], x0.w, y1.w);

        VAD(acc[1][0][0], x1.x, y0.x); VAD(acc[1][0][1], x1.y, y0.y);
        VAD(acc[1][0][0], x1.z, y0.z); VAD(acc[1][0][1], x1.w, y0.w);

        VAD(acc[1][1][0], x1.x, y1.x); VAD(acc[1][1][1], x1.y, y1.y);
        VAD(acc[1][1][0], x1.z, y1.z); VAD(acc[1][1][1], x1.w, y1.w);
    }

    // ---- Stores ----
    float* oblk = out + (size_t)blk * NROW * NROW * 3;

    // L1 = acc / QSCALE  (acc < 2^24, u32->f32 exact)
#pragma unroll
    for (int i = 0; i < 2; i++) {
        const int n = wid * 2 + i;
#pragma unroll
        for (int j = 0; j < 2; j++) {
            const int m = lid + 32 * j;
            float l1v = (float)(acc[i][j][0] + acc[i][j][1]) * RQS;
            oblk[(size_t)(n * NROW + m) * 3 + 2] = l1v;
        }
    }

    // cos / l2 from MMA fragments
    {
        const int rn_[2] = {n0 + g_, n0 + g_ + 8};
        const int cm_[2] = {m0 + 2 * tg, m0 + 2 * tg + 1};
        const float cv[2][2] = {{c0, c1}, {c2, c3}};
#pragma unroll
        for (int i = 0; i < 2; i++) {
            const int n = rn_[i];
            const float xn2 = nx2[n];
            const float rxn = rnx[n];
#pragma unroll
            for (int j = 0; j < 2; j++) {
                const int m = cm_[j];
                const float dotv = cv[i][j];
                float l2v = sqrtf(fmaxf(xn2 + ny2[m] - 2.0f * dotv, 0.0f));
                float cosv = dotv * rxn * rny[m];
                float* o = oblk + (size_t)(n * NROW + m) * 3;
                o[0] = cosv;
                o[1] = l2v;
            }
        }
    }
}

extern "C" void kernel_launch(void* const* d_in, const int* in_sizes, int n_in,
                              void* d_out, int out_size) {
    const float* X = (const float*)d_in[0];
    const float* Y = (const float*)d_in[1];
    float* out = (float*)d_out;

    const int smem_bytes = SMEM_FLOATS * (int)sizeof(float);   // ~103 KB
    cudaFuncSetAttribute(vcmp_kernel, cudaFuncAttributeMaxDynamicSharedMemorySize,
                         smem_bytes);
    vcmp_kernel<<<NBLK, NTHR, smem_bytes>>>(X, Y, out);
}

// round 13
// speedup vs baseline: 2.3390x; 2.3390x over previous
#include <cuda_runtime.h>
#include <cuda_fp16.h>
#include <cstdint>

// Problem constants: S=16, P=8, N=64, D=128
#define NBLK   128
#define NROW   64
#define DIMD   128
#define STRIDE 132     // fp32 row stride (floats)
#define QH     68      // half2 row stride (half2 units; 68 mod 32 == 4 -> conflict-free LDS.128)
#define NTHR   1024

// smem floats: sx[64][132], sy[64][132], nx2/rnx/ny2/rny/sxs/sys[64], qx[64][68](h2), qy[64][68](h2)
#define SMEM_FLOATS (2 * NROW * STRIDE + 6 * NROW + 2 * NROW * QH)

__device__ __forceinline__ __half2 asH2(uint32_t u) {
    __half2 h;
    *(uint32_t*)&h = u;
    return h;
}

__global__ void __launch_bounds__(NTHR, 1)
vcmp_kernel(const float* __restrict__ X, const float* __restrict__ Y,
            float* __restrict__ out) {
    extern __shared__ float smem[];
    float* sx  = smem;
    float* sy  = smem + NROW * STRIDE;
    float* nx2 = sy + NROW * STRIDE;
    float* rnx = nx2 + NROW;
    float* ny2 = rnx + NROW;
    float* rny = ny2 + NROW;
    float* sxs = rny + NROW;                       // row sums of x (fp16-rounded)
    float* sys = sxs + NROW;                       // row sums of y (fp16-rounded)
    uint32_t* qx = (uint32_t*)(sys + NROW);        // half2 rows
    uint32_t* qy = qx + NROW * QH;

    const int blk = blockIdx.x;
    const int t   = threadIdx.x;
    const int wid = t >> 5;
    const int lid = t & 31;

    // ---- Load x, y -> fp32 smem (MMA + norms) and half2 smem (L1 loop) ----
    const float4* xg = (const float4*)(X + (size_t)blk * NROW * DIMD);
    const float4* yg = (const float4*)(Y + (size_t)blk * NROW * DIMD);
#pragma unroll
    for (int k = 0; k < 2; k++) {
        int g    = k * NTHR + t;    // float4 index, 0..2047
        int row  = g >> 5;
        int col4 = (g & 31) * 4;
        float4 xv = xg[g];
        float4 yv = yg[g];
        *(float4*)(sx + row * STRIDE + col4) = xv;
        *(float4*)(sy + row * STRIDE + col4) = yv;

        __half2 hx0 = __float22half2_rn(make_float2(xv.x, xv.y));
        __half2 hx1 = __float22half2_rn(make_float2(xv.z, xv.w));
        __half2 hy0 = __float22half2_rn(make_float2(yv.x, yv.y));
        __half2 hy1 = __float22half2_rn(make_float2(yv.z, yv.w));
        uint2 ux = make_uint2(*(uint32_t*)&hx0, *(uint32_t*)&hx1);
        uint2 uy = make_uint2(*(uint32_t*)&hy0, *(uint32_t*)&hy1);
        *(uint2*)(qx + row * QH + (g & 31) * 2) = ux;
        *(uint2*)(qy + row * QH + (g & 31) * 2) = uy;
    }
    __syncthreads();

    // ---- Norms (t<128, fp32 rows) and row sums of fp16-rounded data (t in [128,256)) ----
    if (t < 128) {
        const float* r = (t < NROW) ? (sx + t * STRIDE) : (sy + (t - NROW) * STRIDE);
        float ss = 0.f;
#pragma unroll 8
        for (int d = 0; d < DIMD; d++) ss = fmaf(r[d], r[d], ss);
        float rn = 1.0f / fmaxf(sqrtf(ss), 1e-12f);
        if (t < NROW) { nx2[t] = ss; rnx[t] = rn; }
        else          { ny2[t - NROW] = ss; rny[t - NROW] = rn; }
    } else if (t < 256) {
        const int r_ = t - 128;
        const uint32_t* q = (r_ < NROW) ? (qx + r_ * QH) : (qy + (r_ - NROW) * QH);
        float s = 0.f;
#pragma unroll 8
        for (int c = 0; c < 64; c++) {
            float2 f = __half22float2(asH2(q[c]));
            s += f.x + f.y;
        }
        if (r_ < NROW) sxs[r_] = s;
        else           sys[r_ - NROW] = s;
    }
    __syncthreads();

    // ---- Gram via mma.sync m16n8k8 tf32 (R6-proven): C = dot(x_n, y_m) ----
    const int g_ = lid >> 2;
    const int tg = lid & 3;
    const int n0 = (wid >> 3) * 16;
    const int m0 = (wid & 7) * 8;

    float c0 = 0.f, c1 = 0.f, c2 = 0.f, c3 = 0.f;
    {
        const uint32_t* pa = (const uint32_t*)(sx + (n0 + g_) * STRIDE + tg);
        const uint32_t* pb = (const uint32_t*)(sy + (m0 + g_) * STRIDE + tg);
#pragma unroll
        for (int kk = 0; kk < 16; kk++) {
            const int d0 = kk * 8;
            uint32_t a0 = pa[d0];
            uint32_t a1 = pa[8 * STRIDE + d0];
            uint32_t a2 = pa[d0 + 4];
            uint32_t a3 = pa[8 * STRIDE + d0 + 4];
            uint32_t b0 = pb[d0];
            uint32_t b1 = pb[d0 + 4];
            asm volatile(
                "mma.sync.aligned.m16n8k8.row.col.f32.tf32.tf32.f32 "
                "{%0,%1,%2,%3}, {%4,%5,%6,%7}, {%8,%9}, {%0,%1,%2,%3};"
                : "+f"(c0), "+f"(c1), "+f"(c2), "+f"(c3)
                : "r"(a0), "r"(a1), "r"(a2), "r"(a3), "r"(b0), "r"(b1));
        }
    }

    // ---- L1 loop: fp16 Sum(max). 1 hmax2 + 1 hadd2 per 2 elements per pair ----
    // n = 2*wid + i, m = lid + 32*j; x broadcast, y conflict-free (QH mod 32 == 4)
    const uint32_t* xq0 = qx + (wid * 2) * QH;
    const uint32_t* xq1 = xq0 + QH;
    const uint32_t* yq0 = qy + lid * QH;
    const uint32_t* yq1 = yq0 + 32 * QH;

    __half2 acc[2][2][4];
#pragma unroll
    for (int i = 0; i < 2; i++)
#pragma unroll
        for (int j = 0; j < 2; j++)
#pragma unroll
            for (int k = 0; k < 4; k++) acc[i][j][k] = __float2half2_rn(0.f);

#pragma unroll
    for (int d2 = 0; d2 < 64; d2 += 4) {   // 16 iterations; 4 half2 per row per iter
        uint4 ux0 = *(const uint4*)(xq0 + d2);
        uint4 ux1 = *(const uint4*)(xq1 + d2);
        uint4 uy0 = *(const uint4*)(yq0 + d2);
        uint4 uy1 = *(const uint4*)(yq1 + d2);
        const uint32_t x0w[4] = {ux0.x, ux0.y, ux0.z, ux0.w};
        const uint32_t x1w[4] = {ux1.x, ux1.y, ux1.z, ux1.w};
        const uint32_t y0w[4] = {uy0.x, uy0.y, uy0.z, uy0.w};
        const uint32_t y1w[4] = {uy1.x, uy1.y, uy1.z, uy1.w};
#pragma unroll
        for (int k = 0; k < 4; k++) {
            __half2 hx0 = asH2(x0w[k]), hx1 = asH2(x1w[k]);
            __half2 hy0 = asH2(y0w[k]), hy1 = asH2(y1w[k]);
            acc[0][0][k] = __hadd2(acc[0][0][k], __hmax2(hx0, hy0));
            acc[0][1][k] = __hadd2(acc[0][1][k], __hmax2(hx0, hy1));
            acc[1][0][k] = __hadd2(acc[1][0][k], __hmax2(hx1, hy0));
            acc[1][1][k] = __hadd2(acc[1][1][k], __hmax2(hx1, hy1));
        }
    }

    // ---- Stores ----
    float* oblk = out + (size_t)blk * NROW * NROW * 3;

    // L1 = 2*Sum(max) - Sx - Sy
#pragma unroll
    for (int i = 0; i < 2; i++) {
        const int n = wid * 2 + i;
        const float sxn = sxs[n];
#pragma unroll
        for (int j = 0; j < 2; j++) {
            const int m = lid + 32 * j;
            float tot = 0.f;
#pragma unroll
            for (int k = 0; k < 4; k++) {
                float2 f = __half22float2(acc[i][j][k]);
                tot += f.x + f.y;
            }
            oblk[(size_t)(n * NROW + m) * 3 + 2] = fmaf(2.0f, tot, -(sxn + sys[m]));
        }
    }

    // cos / l2 from MMA fragments
    {
        const int rn_[2] = {n0 + g_, n0 + g_ + 8};
        const int cm_[2] = {m0 + 2 * tg, m0 + 2 * tg + 1};
        const float cv[2][2] = {{c0, c1}, {c2, c3}};
#pragma unroll
        for (int i = 0; i < 2; i++) {
            const int n = rn_[i];
            const float xn2 = nx2[n];
            const float rxn = rnx[n];
#pragma unroll
            for (int j = 0; j < 2; j++) {
                const int m = cm_[j];
                const float dotv = cv[i][j];
                float l2v = sqrtf(fmaxf(xn2 + ny2[m] - 2.0f * dotv, 0.0f));
                float cosv = dotv * rxn * rny[m];
                float* o = oblk + (size_t)(n * NROW + m) * 3;
                o[0] = cosv;
                o[1] = l2v;
            }
        }
    }
}

extern "C" void kernel_launch(void* const* d_in, const int* in_sizes, int n_in,
                              void* d_out, int out_size) {
    const float* X = (const float*)d_in[0];
    const float* Y = (const float*)d_in[1];
    float* out = (float*)d_out;

    const int smem_bytes = SMEM_FLOATS * (int)sizeof(float);   // ~104 KB
    cudaFuncSetAttribute(vcmp_kernel, cudaFuncAttributeMaxDynamicSharedMemorySize,
                         smem_bytes);
    vcmp_kernel<<<NBLK, NTHR, smem_bytes>>>(X, Y, out);
}